// round 13
// baseline (speedup 1.0000x reference)
#include <cuda_runtime.h>
#include <cuda_bf16.h>
#include <math.h>
#include <stdint.h>

#define Bz 512
#define Sz 100
#define Ez 256
#define Hz 256
#define G4 1024
#define C_EXPLORE 10.0f
#define PARTITIONABLE 1
#define BPB 8          // batch rows per block
#define NBLK (Bz / BPB)

typedef unsigned long long u64;

// ---------------- packed f32x2 helpers (sm_100+) ----------------
__device__ __forceinline__ u64 pk2(float lo, float hi) {
    u64 d; asm("mov.b64 %0, {%1, %2};" : "=l"(d) : "f"(lo), "f"(hi)); return d;
}
__device__ __forceinline__ void upk2(u64 v, float& lo, float& hi) {
    asm("mov.b64 {%0, %1}, %2;" : "=f"(lo), "=f"(hi) : "l"(v));
}
__device__ __forceinline__ u64 fma2(u64 a, u64 b, u64 c) {
    u64 d; asm("fma.rn.f32x2 %0, %1, %2, %3;" : "=l"(d) : "l"(a), "l"(b), "l"(c)); return d;
}

// ---------------- fast exact-enough tanh (Eigen/XLA rational + rcp NR) ----------------
__device__ __forceinline__ float xtanh(float x) {
    const float c = 7.90531110763549805f;
    float cx = fminf(fmaxf(x, -c), c);
    float r = cx * cx;
    float p = -2.76076847742355e-16f;
    p = fmaf(p, r, 2.00018790482477e-13f);
    p = fmaf(p, r, -8.60467152213735e-11f);
    p = fmaf(p, r, 5.12229709037114e-08f);
    p = fmaf(p, r, 1.48572235717979e-05f);
    p = fmaf(p, r, 6.37261928875436e-04f);
    p = fmaf(p, r, 4.89352455891786e-03f);
    float num = cx * p;
    float q = 1.19825839466702e-06f;
    q = fmaf(q, r, 1.18534705686654e-04f);
    q = fmaf(q, r, 2.26843463243900e-03f);
    q = fmaf(q, r, 4.89352518554385e-03f);
    float ri;
    asm("rcp.approx.f32 %0, %1;" : "=f"(ri) : "f"(q));
    ri = ri * fmaf(-q, ri, 2.0f);
    return num * ri;
}
__device__ __forceinline__ float sigf(float x) {
    return 0.5f + 0.5f * xtanh(0.5f * x);
}

// ---------------- device state ----------------
__device__ float g_h0[Bz * Hz];
__device__ float g_c[Bz * Hz];
__device__ float g_enc[(size_t)Bz * Sz * Hz];
__device__ float g_refg[(size_t)Bz * Sz * Hz];
__device__ float g_refp[(size_t)Bz * Sz * Hz];
__device__ float g_Penc[2 * G4];
__device__ float g_Pdec[2 * G4];
__device__ float g_startproj[G4];
__device__ float4 g_WTe[64 * G4];   // [k4][row]
__device__ float4 g_WTd[64 * G4];

// ---------------- threefry2x32 ----------------
__device__ __forceinline__ unsigned rotl32(unsigned v, int r) {
    return (v << r) | (v >> (32 - r));
}
__device__ __forceinline__ void tf2x32(unsigned k0, unsigned k1,
                                       unsigned x0, unsigned x1,
                                       unsigned& o0, unsigned& o1) {
    unsigned ks2 = 0x1BD11BDAu ^ k0 ^ k1;
    x0 += k0; x1 += k1;
#define TF_G(a,b,c,d) \
    x0 += x1; x1 = rotl32(x1,a); x1 ^= x0; \
    x0 += x1; x1 = rotl32(x1,b); x1 ^= x0; \
    x0 += x1; x1 = rotl32(x1,c); x1 ^= x0; \
    x0 += x1; x1 = rotl32(x1,d); x1 ^= x0;
    TF_G(13,15,26,6);  x0 += k1;  x1 += ks2 + 1u;
    TF_G(17,29,16,24); x0 += ks2; x1 += k0 + 2u;
    TF_G(13,15,26,6);  x0 += k0;  x1 += k1 + 3u;
    TF_G(17,29,16,24); x0 += k1;  x1 += ks2 + 4u;
    TF_G(13,15,26,6);  x0 += ks2; x1 += k0 + 5u;
#undef TF_G
    o0 = x0; o1 = x1;
}

// ---------------- setup ----------------
__global__ void k_prep(const float* __restrict__ emb,
                       const float* __restrict__ eWih,
                       const float* __restrict__ dWih,
                       const float* __restrict__ start) {
    int j = blockIdx.x * 256 + threadIdx.x;
    if (j >= G4) return;
    float pe0 = 0.f, pe1 = 0.f, pd0 = 0.f, pd1 = 0.f, sp = 0.f;
    for (int e = 0; e < Ez; e++) {
        float we = eWih[j * Ez + e], wd = dWih[j * Ez + e];
        pe0 = fmaf(emb[e], we, pe0);
        pe1 = fmaf(emb[Ez + e], we, pe1);
        pd0 = fmaf(emb[e], wd, pd0);
        pd1 = fmaf(emb[Ez + e], wd, pd1);
        sp  = fmaf(start[e], wd, sp);
    }
    g_Penc[j] = pe0; g_Penc[G4 + j] = pe1;
    g_Pdec[j] = pd0; g_Pdec[G4 + j] = pd1;
    g_startproj[j] = sp;
}

__global__ void k_tr(const float* __restrict__ eWhh, const float* __restrict__ dWhh) {
    int idx = blockIdx.x * 256 + threadIdx.x;
    const float* W = blockIdx.y ? dWhh : eWhh;
    float4* O = blockIdx.y ? g_WTd : g_WTe;
    int j = idx & (G4 - 1);
    int k4 = idx >> 10;
    O[idx] = *(const float4*)&W[(size_t)j * Hz + (k4 << 2)];
}

// ---------------- gates matvec for BPB=8 b's (bit-identical k-order) ----------------
// hp[p][k] packs b-pair (2p, 2p+1). Writes gat[(g*BPB + b)*256 + jj].
__device__ __forceinline__ void gates8(const float4* __restrict__ wt,
                                       const u64 hp[4][Hz] , float* gat, int tid) {
    u64 ac[4];
#pragma unroll
    for (int p = 0; p < 4; p++) ac[p] = pk2(0.f, 0.f);
#pragma unroll 4
    for (int k4 = 0; k4 < 64; k4++) {
        float4 wv = wt[(k4 << 10) + tid];
        int k = k4 << 2;
        u64 w2;
        w2 = pk2(wv.x, wv.x);
#pragma unroll
        for (int p = 0; p < 4; p++) ac[p] = fma2(w2, hp[p][k], ac[p]);
        w2 = pk2(wv.y, wv.y);
#pragma unroll
        for (int p = 0; p < 4; p++) ac[p] = fma2(w2, hp[p][k + 1], ac[p]);
        w2 = pk2(wv.z, wv.z);
#pragma unroll
        for (int p = 0; p < 4; p++) ac[p] = fma2(w2, hp[p][k + 2], ac[p]);
        w2 = pk2(wv.w, wv.w);
#pragma unroll
        for (int p = 0; p < 4; p++) ac[p] = fma2(w2, hp[p][k + 3], ac[p]);
    }
    int g = tid >> 8, jj = tid & 255;
#pragma unroll
    for (int p = 0; p < 4; p++) {
        float lo, hi;
        upk2(ac[p], lo, hi);
        gat[(g * BPB + 2 * p) * 256 + jj] = lo;
        gat[(g * BPB + 2 * p + 1) * 256 + jj] = hi;
    }
}

// ---------------- persistent encoder: 64 blocks x 1024 thr, 8 b per block ----------------
struct __align__(16) SmemEnc {
    float hh[BPB][Hz];
    float cc[BPB][Hz];
    u64 hp[4][Hz];
    float gat[4 * BPB * Hz];
    float sbias[G4];
    float P0[G4], P1[G4];
};

__global__ void __launch_bounds__(1024, 1) k_enc_p(const float* __restrict__ inp,
                                                   const float* __restrict__ bih,
                                                   const float* __restrict__ bhh) {
    extern __shared__ char smraw[];
    SmemEnc* sm = (SmemEnc*)smraw;
    const int tid = threadIdx.x;
    const int bb = blockIdx.x * BPB;
    const int oct = tid >> 7, ht = tid & 127;
    const int b = bb + oct;

#pragma unroll
    for (int r = 0; r < 2; r++) {
        sm->hh[oct][ht + r * 128] = 0.f;
        sm->cc[oct][ht + r * 128] = 0.f;
    }
    sm->sbias[tid] = bih[tid] + bhh[tid];
    sm->P0[tid] = g_Penc[tid];
    sm->P1[tid] = g_Penc[G4 + tid];
    __syncthreads();

    const float4* wt = g_WTe;
    for (int t = 0; t < Sz; t++) {
        {
            int p = tid >> 8, hx = tid & 255;
            sm->hp[p][hx] = pk2(sm->hh[2 * p][hx], sm->hh[2 * p + 1][hx]);
        }
        __syncthreads();
        gates8(wt, sm->hp, sm->gat, tid);
        __syncthreads();
        // cell: thread (b=oct, hx in {ht, ht+128})
        float c0 = inp[(b * 2) * Sz + t];
        float c1 = inp[(b * 2 + 1) * Sz + t];
#pragma unroll
        for (int r = 0; r < 2; r++) {
            int hx = ht + r * 128;
            float a0 = sm->gat[(0 * BPB + oct) * 256 + hx];
            float a1 = sm->gat[(1 * BPB + oct) * 256 + hx];
            float a2 = sm->gat[(2 * BPB + oct) * 256 + hx];
            float a3 = sm->gat[(3 * BPB + oct) * 256 + hx];
            float gi = a0 + fmaf(c0, sm->P0[hx],       c1 * sm->P1[hx])       + sm->sbias[hx];
            float gf = a1 + fmaf(c0, sm->P0[256 + hx], c1 * sm->P1[256 + hx]) + sm->sbias[256 + hx];
            float gc = a2 + fmaf(c0, sm->P0[512 + hx], c1 * sm->P1[512 + hx]) + sm->sbias[512 + hx];
            float go = a3 + fmaf(c0, sm->P0[768 + hx], c1 * sm->P1[768 + hx]) + sm->sbias[768 + hx];
            float nc = sigf(gf) * sm->cc[oct][hx] + sigf(gi) * xtanh(gc);
            sm->cc[oct][hx] = nc;
            float nh = sigf(go) * xtanh(nc);
            sm->hh[oct][hx] = nh;
            g_enc[((size_t)b * Sz + t) * Hz + hx] = nh;
        }
        __syncthreads();
    }
#pragma unroll
    for (int r = 0; r < 2; r++) {
        int hx = ht + r * 128;
        g_h0[(b << 8) + hx] = sm->hh[oct][hx];
        g_c[(b << 8) + hx] = sm->cc[oct][hx];
    }
}

// ---------------- ref projections (z=0: glimpse, z=1: pointer) ----------------
__global__ void __launch_bounds__(256) k_ref(const float* __restrict__ gWr,
                                             const float* __restrict__ gbr,
                                             const float* __restrict__ pWr,
                                             const float* __restrict__ pbr) {
    __shared__ float As[16][64];
    __shared__ float Ws[16][64];
    const float* A = g_enc;
    const float* W = blockIdx.z ? pWr : gWr;
    const float* bias = blockIdx.z ? pbr : gbr;
    float* C = blockIdx.z ? g_refp : g_refg;
    const int K = Hz, N = Hz;
    const int bm = blockIdx.y * 64;
    const int bn = blockIdx.x * 64;
    const int t = threadIdx.x;
    const int tx = t & 15, ty = t >> 4;
    const int lr = t >> 2, lc = (t & 3) << 2;
    float acc[4][4];
#pragma unroll
    for (int i = 0; i < 4; i++)
#pragma unroll
        for (int jj = 0; jj < 4; jj++) acc[i][jj] = 0.f;
    const float* Ab = A + (size_t)(bm + lr) * K + lc;
    const float* Wb = W + (size_t)(bn + lr) * K + lc;
    for (int k0 = 0; k0 < K; k0 += 16) {
        float4 av = *(const float4*)(Ab + k0);
        float4 wv = *(const float4*)(Wb + k0);
        As[lc + 0][lr] = av.x; As[lc + 1][lr] = av.y;
        As[lc + 2][lr] = av.z; As[lc + 3][lr] = av.w;
        Ws[lc + 0][lr] = wv.x; Ws[lc + 1][lr] = wv.y;
        Ws[lc + 2][lr] = wv.z; Ws[lc + 3][lr] = wv.w;
        __syncthreads();
#pragma unroll
        for (int k = 0; k < 16; k++) {
            float4 a4 = *(const float4*)&As[k][ty << 2];
            float4 w4 = *(const float4*)&Ws[k][tx << 2];
            float am[4] = {a4.x, a4.y, a4.z, a4.w};
            float wn[4] = {w4.x, w4.y, w4.z, w4.w};
#pragma unroll
            for (int i = 0; i < 4; i++)
#pragma unroll
                for (int jj = 0; jj < 4; jj++)
                    acc[i][jj] = fmaf(am[i], wn[jj], acc[i][jj]);
        }
        __syncthreads();
    }
#pragma unroll
    for (int i = 0; i < 4; i++) {
        int m = bm + (ty << 2) + i;
#pragma unroll
        for (int jj = 0; jj < 4; jj++) {
            int n = bn + (tx << 2) + jj;
            C[(size_t)m * N + n] = acc[i][jj] + bias[n];
        }
    }
}

__device__ __forceinline__ void wredd4(float& a0, float& a1, float& a2, float& a3) {
#pragma unroll
    for (int o = 16; o; o >>= 1) {
        a0 += __shfl_xor_sync(0xffffffffu, a0, o);
        a1 += __shfl_xor_sync(0xffffffffu, a1, o);
        a2 += __shfl_xor_sync(0xffffffffu, a2, o);
        a3 += __shfl_xor_sync(0xffffffffu, a3, o);
    }
}

// ---------------- persistent decoder smem ----------------
struct __align__(16) SmemDec {
    float hh[BPB][Hz];
    float cc[BPB][Hz];
    u64 hp[4][Hz];
    float gat[4 * BPB * Hz];
    float sbias[G4];
    float P0[G4], P1[G4];
    float qq[BPB][Hz];
    float qv[BPB][Hz];
    float Vg[Hz], Vp[Hz];
    float lg[BPB][128];
    float w[BPB][128];
    float red[BPB][128];
    int ridx[BPB][128];
    short list[BPB][104];
    unsigned char m[BPB][104];
    int ccnt[BPB][4];
    int idx[BPB];
};

// ---------------- persistent decoder: 64 blocks x 1024 thr, 8 b/block ----------------
__global__ void __launch_bounds__(1024, 1) k_dec_p(const float* __restrict__ inp,
                                                   const float* __restrict__ dbih,
                                                   const float* __restrict__ dbhh,
                                                   const float* __restrict__ gWq,
                                                   const float* __restrict__ gbq,
                                                   const float* __restrict__ gV,
                                                   const float* __restrict__ pWq,
                                                   const float* __restrict__ pbq,
                                                   const float* __restrict__ pV,
                                                   float* __restrict__ out) {
    extern __shared__ char smraw[];
    SmemDec* sm = (SmemDec*)smraw;

    const int tid = threadIdx.x;
    const int bb = blockIdx.x * BPB;
    const int oct = tid >> 7, ht = tid & 127;
    const int wd = tid >> 5, ln = tid & 31;
    const int w4 = wd & 3;               // warp within octant
    const int b = bb + oct;

#pragma unroll
    for (int r = 0; r < 2; r++) {
        int hx = ht + r * 128;
        sm->hh[oct][hx] = g_h0[(b << 8) + hx];
        sm->cc[oct][hx] = g_c[(b << 8) + hx];
    }
    sm->sbias[tid] = dbih[tid] + dbhh[tid];
    sm->P0[tid] = g_Pdec[tid];
    sm->P1[tid] = g_Pdec[G4 + tid];
    if (tid < Hz) sm->Vg[tid] = gV[tid];
    else if (tid < 2 * Hz) sm->Vp[tid - Hz] = pV[tid - Hz];
    if (ht < Sz) sm->m[oct][ht] = 0;
    if (tid < BPB) sm->idx[tid] = 0;
    __syncthreads();

    float* out_probs = out;
    float* out_idx = out + (size_t)Sz * Bz * Sz;
    const float4* wt = g_WTd;

    for (int t = 0; t < Sz; t++) {
        {
            int p = tid >> 8, hx = tid & 255;
            sm->hp[p][hx] = pk2(sm->hh[2 * p][hx], sm->hh[2 * p + 1][hx]);
        }
        __syncthreads();
        gates8(wt, sm->hp, sm->gat, tid);
        __syncthreads();
        // ---- LSTM cell ----
        {
            float xc0 = 0.f, xc1 = 0.f;
            int sfeed = sm->idx[oct];
            if (t > 0) {
                xc0 = inp[(b * 2) * Sz + sfeed];
                xc1 = inp[(b * 2 + 1) * Sz + sfeed];
            }
#pragma unroll
            for (int r = 0; r < 2; r++) {
                int hx = ht + r * 128;
                float a0 = sm->gat[(0 * BPB + oct) * 256 + hx];
                float a1 = sm->gat[(1 * BPB + oct) * 256 + hx];
                float a2 = sm->gat[(2 * BPB + oct) * 256 + hx];
                float a3 = sm->gat[(3 * BPB + oct) * 256 + hx];
                float xg0, xg1, xg2, xg3;
                if (t == 0) {
                    xg0 = g_startproj[hx];
                    xg1 = g_startproj[256 + hx];
                    xg2 = g_startproj[512 + hx];
                    xg3 = g_startproj[768 + hx];
                } else {
                    xg0 = fmaf(xc0, sm->P0[hx],       xc1 * sm->P1[hx]);
                    xg1 = fmaf(xc0, sm->P0[256 + hx], xc1 * sm->P1[256 + hx]);
                    xg2 = fmaf(xc0, sm->P0[512 + hx], xc1 * sm->P1[512 + hx]);
                    xg3 = fmaf(xc0, sm->P0[768 + hx], xc1 * sm->P1[768 + hx]);
                }
                float gi = a0 + xg0 + sm->sbias[hx];
                float gf = a1 + xg1 + sm->sbias[256 + hx];
                float gc = a2 + xg2 + sm->sbias[512 + hx];
                float go = a3 + xg3 + sm->sbias[768 + hx];
                float nc = sigf(gf) * sm->cc[oct][hx] + sigf(gi) * xtanh(gc);
                sm->cc[oct][hx] = nc;
                sm->hh[oct][hx] = sigf(go) * xtanh(nc);
            }
        }
        __syncthreads();

        // ---- mask update + compaction (per octant, 128 threads) ----
        if (t > 0 && ht == 0) sm->m[oct][sm->idx[oct]] = 1;
        __syncthreads();
        {
            int chunk = ht >> 5;
            bool un = (ht < Sz) && !sm->m[oct][ht];
            unsigned bal = __ballot_sync(0xffffffffu, un);
            int pre = __popc(bal & ((1u << (ht & 31)) - 1));
            if ((ht & 31) == 0) sm->ccnt[oct][chunk] = __popc(bal);
            __syncthreads();
            if (un) {
                int base = 0;
                for (int i = 0; i < chunk; i++) base += sm->ccnt[oct][i];
                sm->list[oct][base + pre] = (short)ht;
            }
            sm->lg[oct][ht] = -INFINITY;
        }
        __syncthreads();
        const int n_self = sm->ccnt[oct][0] + sm->ccnt[oct][1] + sm->ccnt[oct][2] + sm->ccnt[oct][3];

        // ---- qq = h @ gWq^T + gbq: warp-cooperative, 8 b's per W read ----
        for (int row = wd; row < Hz; row += 32) {
            const float4* wr = (const float4*)(gWq + (size_t)row * Hz);
            float4 w1 = wr[ln], w2 = wr[32 + ln];
            float a[BPB];
#pragma unroll
            for (int g = 0; g < BPB; g++) {
                float4 ha = *(const float4*)&sm->hh[g][ln << 2];
                float4 hb = *(const float4*)&sm->hh[g][128 + (ln << 2)];
                float ag = 0.f;
                ag = fmaf(w1.x, ha.x, ag); ag = fmaf(w1.y, ha.y, ag);
                ag = fmaf(w1.z, ha.z, ag); ag = fmaf(w1.w, ha.w, ag);
                ag = fmaf(w2.x, hb.x, ag); ag = fmaf(w2.y, hb.y, ag);
                ag = fmaf(w2.z, hb.z, ag); ag = fmaf(w2.w, hb.w, ag);
                a[g] = ag;
            }
            wredd4(a[0], a[1], a[2], a[3]);
            wredd4(a[4], a[5], a[6], a[7]);
            if (!ln) {
                float bq = gbq[row];
#pragma unroll
                for (int g = 0; g < BPB; g++) sm->qq[g][row] = a[g] + bq;
            }
        }
        __syncthreads();
        // ---- glimpse logits: 4 warps per octant over its own compact list ----
        for (int ii = w4; ii < n_self; ii += 4) {
            int s = sm->list[oct][ii];
            const float4* rg = (const float4*)(g_refg + ((size_t)b * Sz + s) * Hz);
            float a = 0.f;
#pragma unroll
            for (int i = 0; i < 2; i++) {
                int cix = i * 32 + ln;
                float4 rv = rg[cix];
                float4 qvv = *(const float4*)&sm->qq[oct][cix << 2];
                float4 vv = *(const float4*)&sm->Vg[cix << 2];
                a = fmaf(vv.x, xtanh(qvv.x + rv.x), a);
                a = fmaf(vv.y, xtanh(qvv.y + rv.y), a);
                a = fmaf(vv.z, xtanh(qvv.z + rv.z), a);
                a = fmaf(vv.w, xtanh(qvv.w + rv.w), a);
            }
#pragma unroll
            for (int o = 16; o; o >>= 1) a += __shfl_xor_sync(0xffffffffu, a, o);
            if (!ln) sm->lg[oct][s] = a;
        }
        __syncthreads();
        // ---- softmax -> w (per octant, 128 threads) ----
        {
            float v = (ht < Sz) ? sm->lg[oct][ht] : -INFINITY;
            sm->red[oct][ht] = v; __syncthreads();
#pragma unroll
            for (int o = 64; o; o >>= 1) { if (ht < o) sm->red[oct][ht] = fmaxf(sm->red[oct][ht], sm->red[oct][ht + o]); __syncthreads(); }
            float m = sm->red[oct][0]; __syncthreads();
            float e = (ht < Sz) ? expf(v - m) : 0.f;
            sm->red[oct][ht] = e; __syncthreads();
#pragma unroll
            for (int o = 64; o; o >>= 1) { if (ht < o) sm->red[oct][ht] += sm->red[oct][ht + o]; __syncthreads(); }
            float smv = sm->red[oct][0]; __syncthreads();
            sm->w[oct][ht] = (ht < Sz) ? e / smv : 0.f;
        }
        __syncthreads();
        // ---- q = sum over unmasked s of w[s]*enc[b,s,:] (2 h per thread) ----
#pragma unroll
        for (int r = 0; r < 2; r++) {
            int hx = ht + r * 128;
            float av[8];
#pragma unroll
            for (int i = 0; i < 8; i++) av[i] = 0.f;
            const float* eb = g_enc + (size_t)b * Sz * Hz + hx;
            int ii = 0;
            for (; ii + 8 <= n_self; ii += 8) {
#pragma unroll
                for (int i = 0; i < 8; i++) {
                    int s = sm->list[oct][ii + i];
                    av[i] = fmaf(sm->w[oct][s], eb[(size_t)s * Hz], av[i]);
                }
            }
            for (; ii < n_self; ii++) {
                int s = sm->list[oct][ii];
                av[ii & 7] = fmaf(sm->w[oct][s], eb[(size_t)s * Hz], av[ii & 7]);
            }
            sm->qv[oct][hx] = ((av[0] + av[1]) + (av[2] + av[3])) + ((av[4] + av[5]) + (av[6] + av[7]));
        }
        __syncthreads();
        // ---- qq2 = q @ pWq^T + pbq ----
        for (int row = wd; row < Hz; row += 32) {
            const float4* wr = (const float4*)(pWq + (size_t)row * Hz);
            float4 w1 = wr[ln], w2 = wr[32 + ln];
            float a[BPB];
#pragma unroll
            for (int g = 0; g < BPB; g++) {
                float4 ha = *(const float4*)&sm->qv[g][ln << 2];
                float4 hb = *(const float4*)&sm->qv[g][128 + (ln << 2)];
                float ag = 0.f;
                ag = fmaf(w1.x, ha.x, ag); ag = fmaf(w1.y, ha.y, ag);
                ag = fmaf(w1.z, ha.z, ag); ag = fmaf(w1.w, ha.w, ag);
                ag = fmaf(w2.x, hb.x, ag); ag = fmaf(w2.y, hb.y, ag);
                ag = fmaf(w2.z, hb.z, ag); ag = fmaf(w2.w, hb.w, ag);
                a[g] = ag;
            }
            wredd4(a[0], a[1], a[2], a[3]);
            wredd4(a[4], a[5], a[6], a[7]);
            if (!ln) {
                float bq = pbq[row];
#pragma unroll
                for (int g = 0; g < BPB; g++) sm->qq[g][row] = a[g] + bq;
            }
        }
        __syncthreads();
        // ---- pointer logits ----
        for (int ii = w4; ii < n_self; ii += 4) {
            int s = sm->list[oct][ii];
            const float4* rp = (const float4*)(g_refp + ((size_t)b * Sz + s) * Hz);
            float a = 0.f;
#pragma unroll
            for (int i = 0; i < 2; i++) {
                int cix = i * 32 + ln;
                float4 rv = rp[cix];
                float4 qvv = *(const float4*)&sm->qq[oct][cix << 2];
                float4 vv = *(const float4*)&sm->Vp[cix << 2];
                a = fmaf(vv.x, xtanh(qvv.x + rv.x), a);
                a = fmaf(vv.y, xtanh(qvv.y + rv.y), a);
                a = fmaf(vv.z, xtanh(qvv.z + rv.z), a);
                a = fmaf(vv.w, xtanh(qvv.w + rv.w), a);
            }
#pragma unroll
            for (int o = 16; o; o >>= 1) a += __shfl_xor_sync(0xffffffffu, a, o);
            if (!ln) sm->lg[oct][s] = C_EXPLORE * xtanh(a);
        }
        __syncthreads();
        // ---- softmax -> probs; gumbel argmax -> idx (per octant) ----
        {
            float v = (ht < Sz) ? sm->lg[oct][ht] : -INFINITY;
            sm->red[oct][ht] = v; __syncthreads();
#pragma unroll
            for (int o = 64; o; o >>= 1) { if (ht < o) sm->red[oct][ht] = fmaxf(sm->red[oct][ht], sm->red[oct][ht + o]); __syncthreads(); }
            float m = sm->red[oct][0]; __syncthreads();
            float e = (ht < Sz) ? expf(v - m) : 0.f;
            sm->red[oct][ht] = e; __syncthreads();
#pragma unroll
            for (int o = 64; o; o >>= 1) { if (ht < o) sm->red[oct][ht] += sm->red[oct][ht + o]; __syncthreads(); }
            float smv = sm->red[oct][0]; __syncthreads();
            if (ht < Sz)
                out_probs[(size_t)t * Bz * Sz + (size_t)b * Sz + ht] = e / smv;
            float pv = -INFINITY;
            if (ht < Sz) {
                unsigned key0, key1;
#if PARTITIONABLE
                tf2x32(0u, 1u, 0u, (unsigned)t, key0, key1);
#else
                {
                    unsigned a0k, b0k;
                    unsigned idx0 = 2u * t, idx1 = 2u * t + 1u;
                    if (idx0 < Sz) { tf2x32(0u, 1u, idx0, idx0 + Sz, a0k, b0k); key0 = a0k; }
                    else           { tf2x32(0u, 1u, idx0 - Sz, idx0, a0k, b0k); key0 = b0k; }
                    if (idx1 < Sz) { tf2x32(0u, 1u, idx1, idx1 + Sz, a0k, b0k); key1 = a0k; }
                    else           { tf2x32(0u, 1u, idx1 - Sz, idx1, a0k, b0k); key1 = b0k; }
                }
#endif
                unsigned m0 = (unsigned)(b * Sz + ht);
                unsigned ra, rb, bits;
#if PARTITIONABLE
                tf2x32(key0, key1, 0u, m0, ra, rb);
                bits = ra ^ rb;
#else
                const unsigned halfn = (Bz * Sz) / 2;
                if (m0 < halfn) { tf2x32(key0, key1, m0, m0 + halfn, ra, rb); bits = ra; }
                else            { tf2x32(key0, key1, m0 - halfn, m0, ra, rb); bits = rb; }
#endif
                float f = __uint_as_float((bits >> 9) | 0x3f800000u) - 1.0f;
                float u = fmaxf(f, 1.17549435e-38f);
                pv = v - logf(-logf(u));
            }
            sm->red[oct][ht] = pv; sm->ridx[oct][ht] = ht; __syncthreads();
#pragma unroll
            for (int o = 64; o; o >>= 1) {
                if (ht < o) {
                    float a2 = sm->red[oct][ht], c2 = sm->red[oct][ht + o];
                    int ia = sm->ridx[oct][ht], ic = sm->ridx[oct][ht + o];
                    if (c2 > a2 || (c2 == a2 && ic < ia)) { sm->red[oct][ht] = c2; sm->ridx[oct][ht] = ic; }
                }
                __syncthreads();
            }
            if (!ht) {
                int id = sm->ridx[oct][0];
                sm->idx[oct] = id;
                out_idx[(size_t)t * Bz + b] = (float)id;
            }
        }
        __syncthreads();
    }
}

// ---------------- host ----------------
extern "C" void kernel_launch(void* const* d_in, const int* in_sizes, int n_in,
                              void* d_out, int out_size) {
    const float* in_inputs = (const float*)d_in[0];
    const float* in_emb    = (const float*)d_in[1];
    const float* in_eWih   = (const float*)d_in[2];
    const float* in_eWhh   = (const float*)d_in[3];
    const float* in_ebih   = (const float*)d_in[4];
    const float* in_ebhh   = (const float*)d_in[5];
    const float* in_dWih   = (const float*)d_in[6];
    const float* in_dWhh   = (const float*)d_in[7];
    const float* in_dbih   = (const float*)d_in[8];
    const float* in_dbhh   = (const float*)d_in[9];
    const float* in_gWq    = (const float*)d_in[10];
    const float* in_gbq    = (const float*)d_in[11];
    const float* in_gWr    = (const float*)d_in[12];
    const float* in_gbr    = (const float*)d_in[13];
    const float* in_gV     = (const float*)d_in[14];
    const float* in_pWq    = (const float*)d_in[15];
    const float* in_pbq    = (const float*)d_in[16];
    const float* in_pWr    = (const float*)d_in[17];
    const float* in_pbr    = (const float*)d_in[18];
    const float* in_pV     = (const float*)d_in[19];
    const float* in_start  = (const float*)d_in[20];
    float* out = (float*)d_out;

    cudaFuncSetAttribute(k_dec_p, cudaFuncAttributeMaxDynamicSharedMemorySize,
                         (int)sizeof(SmemDec));
    cudaFuncSetAttribute(k_enc_p, cudaFuncAttributeMaxDynamicSharedMemorySize,
                         (int)sizeof(SmemEnc));

    k_prep<<<4, 256>>>(in_emb, in_eWih, in_dWih, in_start);
    {
        dim3 grid(256, 2);
        k_tr<<<grid, 256>>>(in_eWhh, in_dWhh);
    }
    k_enc_p<<<NBLK, 1024, sizeof(SmemEnc)>>>(in_inputs, in_ebih, in_ebhh);
    {
        dim3 grid(Hz / 64, (Bz * Sz) / 64, 2);
        k_ref<<<grid, 256>>>(in_gWr, in_gbr, in_pWr, in_pbr);
    }
    k_dec_p<<<NBLK, 1024, sizeof(SmemDec)>>>(in_inputs, in_dbih, in_dbhh,
                                             in_gWq, in_gbq, in_gV,
                                             in_pWq, in_pbq, in_pV, out);
    (void)in_sizes; (void)n_in; (void)out_size;
}

// round 14
// speedup vs baseline: 1.6900x; 1.6900x over previous
#include <cuda_runtime.h>
#include <cuda_bf16.h>
#include <math.h>
#include <stdint.h>

#define Bz 512
#define Sz 100
#define Ez 256
#define Hz 256
#define G4 1024
#define C_EXPLORE 10.0f
#define PARTITIONABLE 1

typedef unsigned long long u64;

// ---------------- packed f32x2 helpers (sm_100+) ----------------
__device__ __forceinline__ u64 pk2(float lo, float hi) {
    u64 d; asm("mov.b64 %0, {%1, %2};" : "=l"(d) : "f"(lo), "f"(hi)); return d;
}
__device__ __forceinline__ void upk2(u64 v, float& lo, float& hi) {
    asm("mov.b64 {%0, %1}, %2;" : "=f"(lo), "=f"(hi) : "l"(v));
}
__device__ __forceinline__ u64 fma2(u64 a, u64 b, u64 c) {
    u64 d; asm("fma.rn.f32x2 %0, %1, %2, %3;" : "=l"(d) : "l"(a), "l"(b), "l"(c)); return d;
}

// ---------------- fast exact-enough tanh (Eigen/XLA rational + rcp NR) ----------------
__device__ __forceinline__ float xtanh(float x) {
    const float c = 7.90531110763549805f;
    float cx = fminf(fmaxf(x, -c), c);
    float r = cx * cx;
    float p = -2.76076847742355e-16f;
    p = fmaf(p, r, 2.00018790482477e-13f);
    p = fmaf(p, r, -8.60467152213735e-11f);
    p = fmaf(p, r, 5.12229709037114e-08f);
    p = fmaf(p, r, 1.48572235717979e-05f);
    p = fmaf(p, r, 6.37261928875436e-04f);
    p = fmaf(p, r, 4.89352455891786e-03f);
    float num = cx * p;
    float q = 1.19825839466702e-06f;
    q = fmaf(q, r, 1.18534705686654e-04f);
    q = fmaf(q, r, 2.26843463243900e-03f);
    q = fmaf(q, r, 4.89352518554385e-03f);
    float ri;
    asm("rcp.approx.f32 %0, %1;" : "=f"(ri) : "f"(q));
    ri = ri * fmaf(-q, ri, 2.0f);
    return num * ri;
}
__device__ __forceinline__ float sigf(float x) {
    return 0.5f + 0.5f * xtanh(0.5f * x);
}

// ---------------- device state ----------------
__device__ float g_h0[Bz * Hz];
__device__ float g_c[Bz * Hz];
__device__ float g_enc[(size_t)Bz * Sz * Hz];
__device__ float g_refg[(size_t)Bz * Sz * Hz];
__device__ float g_refp[(size_t)Bz * Sz * Hz];
__device__ float g_Penc[2 * G4];
__device__ float g_Pdec[2 * G4];
__device__ float g_startproj[G4];
__device__ float4 g_WTe[64 * G4];   // [k4][row]
__device__ float4 g_WTd[64 * G4];

// ---------------- threefry2x32 ----------------
__device__ __forceinline__ unsigned rotl32(unsigned v, int r) {
    return (v << r) | (v >> (32 - r));
}
__device__ __forceinline__ void tf2x32(unsigned k0, unsigned k1,
                                       unsigned x0, unsigned x1,
                                       unsigned& o0, unsigned& o1) {
    unsigned ks2 = 0x1BD11BDAu ^ k0 ^ k1;
    x0 += k0; x1 += k1;
#define TF_G(a,b,c,d) \
    x0 += x1; x1 = rotl32(x1,a); x1 ^= x0; \
    x0 += x1; x1 = rotl32(x1,b); x1 ^= x0; \
    x0 += x1; x1 = rotl32(x1,c); x1 ^= x0; \
    x0 += x1; x1 = rotl32(x1,d); x1 ^= x0;
    TF_G(13,15,26,6);  x0 += k1;  x1 += ks2 + 1u;
    TF_G(17,29,16,24); x0 += ks2; x1 += k0 + 2u;
    TF_G(13,15,26,6);  x0 += k0;  x1 += k1 + 3u;
    TF_G(17,29,16,24); x0 += k1;  x1 += ks2 + 4u;
    TF_G(13,15,26,6);  x0 += ks2; x1 += k0 + 5u;
#undef TF_G
    o0 = x0; o1 = x1;
}

// ---------------- setup ----------------
__global__ void k_prep(const float* __restrict__ emb,
                       const float* __restrict__ eWih,
                       const float* __restrict__ dWih,
                       const float* __restrict__ start) {
    int j = blockIdx.x * 256 + threadIdx.x;
    if (j >= G4) return;
    float pe0 = 0.f, pe1 = 0.f, pd0 = 0.f, pd1 = 0.f, sp = 0.f;
    for (int e = 0; e < Ez; e++) {
        float we = eWih[j * Ez + e], wd = dWih[j * Ez + e];
        pe0 = fmaf(emb[e], we, pe0);
        pe1 = fmaf(emb[Ez + e], we, pe1);
        pd0 = fmaf(emb[e], wd, pd0);
        pd1 = fmaf(emb[Ez + e], wd, pd1);
        sp  = fmaf(start[e], wd, sp);
    }
    g_Penc[j] = pe0; g_Penc[G4 + j] = pe1;
    g_Pdec[j] = pd0; g_Pdec[G4 + j] = pd1;
    g_startproj[j] = sp;
}

// transpose Whh -> k-major float4 tables (one-time)
__global__ void k_tr(const float* __restrict__ eWhh, const float* __restrict__ dWhh) {
    int idx = blockIdx.x * 256 + threadIdx.x;   // 0..65535
    const float* W = blockIdx.y ? dWhh : eWhh;
    float4* O = blockIdx.y ? g_WTd : g_WTe;
    int j = idx & (G4 - 1);
    int k4 = idx >> 10;
    O[idx] = *(const float4*)&W[(size_t)j * Hz + (k4 << 2)];
}

// ---------------- persistent encoder: 128 blocks x 1024 thr, 4 b per block ----------------
__global__ void __launch_bounds__(1024, 1) k_enc_p(const float* __restrict__ inp,
                                                   const float* __restrict__ bih,
                                                   const float* __restrict__ bhh) {
    __shared__ float hh[4][Hz];
    __shared__ float cc[4][Hz];
    __shared__ u64 hp[2][Hz];
    __shared__ float gat[4 * 4 * Hz];   // [g][b][jj]
    __shared__ float sbias[G4];
    __shared__ float P0[G4], P1[G4];

    const int tid = threadIdx.x;
    const int bb = blockIdx.x << 2;
    const int qt = tid >> 8, ht = tid & 255;

    hh[qt][ht] = 0.f;
    cc[qt][ht] = 0.f;
    sbias[tid] = bih[tid] + bhh[tid];
    P0[tid] = g_Penc[tid];
    P1[tid] = g_Penc[G4 + tid];
    __syncthreads();

    const float4* wt = g_WTe;
    for (int t = 0; t < Sz; t++) {
        // pack h pairs
        if (tid < 512) {
            int pr = tid >> 8, hx = tid & 255;
            hp[pr][hx] = pk2(hh[2 * pr][hx], hh[2 * pr + 1][hx]);
        }
        __syncthreads();
        // gates: thread = row (g*256+jj) = tid, accumulate 4 b's
        u64 a01 = pk2(0.f, 0.f), a23 = a01;
#pragma unroll 4
        for (int k4 = 0; k4 < 64; k4++) {
            float4 wv = wt[(k4 << 10) + tid];
            int k = k4 << 2;
            u64 w2;
            w2 = pk2(wv.x, wv.x); a01 = fma2(w2, hp[0][k], a01);     a23 = fma2(w2, hp[1][k], a23);
            w2 = pk2(wv.y, wv.y); a01 = fma2(w2, hp[0][k + 1], a01); a23 = fma2(w2, hp[1][k + 1], a23);
            w2 = pk2(wv.z, wv.z); a01 = fma2(w2, hp[0][k + 2], a01); a23 = fma2(w2, hp[1][k + 2], a23);
            w2 = pk2(wv.w, wv.w); a01 = fma2(w2, hp[0][k + 3], a01); a23 = fma2(w2, hp[1][k + 3], a23);
        }
        {
            float l0, l1, l2, l3;
            upk2(a01, l0, l1);
            upk2(a23, l2, l3);
            int gb = ((tid >> 8) << 10) + (tid & 255);
            gat[gb] = l0; gat[gb + 256] = l1; gat[gb + 512] = l2; gat[gb + 768] = l3;
        }
        __syncthreads();
        // cell: thread (b=qt, hidx=ht)
        {
            float a0 = gat[(qt << 8) + ht];
            float a1 = gat[1024 + (qt << 8) + ht];
            float a2 = gat[2048 + (qt << 8) + ht];
            float a3 = gat[3072 + (qt << 8) + ht];
            int b = bb + qt;
            float c0 = inp[(b * 2) * Sz + t];
            float c1 = inp[(b * 2 + 1) * Sz + t];
            float gi = a0 + fmaf(c0, P0[ht],        c1 * P1[ht])        + sbias[ht];
            float gf = a1 + fmaf(c0, P0[256 + ht],  c1 * P1[256 + ht])  + sbias[256 + ht];
            float gc = a2 + fmaf(c0, P0[512 + ht],  c1 * P1[512 + ht])  + sbias[512 + ht];
            float go = a3 + fmaf(c0, P0[768 + ht],  c1 * P1[768 + ht])  + sbias[768 + ht];
            float nc = sigf(gf) * cc[qt][ht] + sigf(gi) * xtanh(gc);
            cc[qt][ht] = nc;
            float nh = sigf(go) * xtanh(nc);
            hh[qt][ht] = nh;
            g_enc[((size_t)b * Sz + t) * Hz + ht] = nh;
        }
        __syncthreads();
    }
    // handoff to decoder
    {
        int b = bb + qt;
        g_h0[(b << 8) + ht] = hh[qt][ht];
        g_c[(b << 8) + ht] = cc[qt][ht];
    }
}

// ---------------- FUSED ref projections: one A-tile load serves BOTH outputs ----------------
__global__ void __launch_bounds__(256) k_ref2(const float* __restrict__ gWr,
                                              const float* __restrict__ gbr,
                                              const float* __restrict__ pWr,
                                              const float* __restrict__ pbr) {
    __shared__ float As[16][64];
    __shared__ float Wg[16][64];
    __shared__ float Wp[16][64];
    const float* A = g_enc;
    const int K = Hz, N = Hz;
    const int bm = blockIdx.y * 64;
    const int bn = blockIdx.x * 64;
    const int t = threadIdx.x;
    const int tx = t & 15, ty = t >> 4;
    const int lr = t >> 2, lc = (t & 3) << 2;
    float accg[4][4], accp[4][4];
#pragma unroll
    for (int i = 0; i < 4; i++)
#pragma unroll
        for (int jj = 0; jj < 4; jj++) { accg[i][jj] = 0.f; accp[i][jj] = 0.f; }
    const float* Ab = A + (size_t)(bm + lr) * K + lc;
    const float* Wgb = gWr + (size_t)(bn + lr) * K + lc;
    const float* Wpb = pWr + (size_t)(bn + lr) * K + lc;
    for (int k0 = 0; k0 < K; k0 += 16) {
        float4 av = *(const float4*)(Ab + k0);
        float4 gv = *(const float4*)(Wgb + k0);
        float4 pv = *(const float4*)(Wpb + k0);
        As[lc + 0][lr] = av.x; As[lc + 1][lr] = av.y;
        As[lc + 2][lr] = av.z; As[lc + 3][lr] = av.w;
        Wg[lc + 0][lr] = gv.x; Wg[lc + 1][lr] = gv.y;
        Wg[lc + 2][lr] = gv.z; Wg[lc + 3][lr] = gv.w;
        Wp[lc + 0][lr] = pv.x; Wp[lc + 1][lr] = pv.y;
        Wp[lc + 2][lr] = pv.z; Wp[lc + 3][lr] = pv.w;
        __syncthreads();
#pragma unroll
        for (int k = 0; k < 16; k++) {
            float4 a4 = *(const float4*)&As[k][ty << 2];
            float4 g4 = *(const float4*)&Wg[k][tx << 2];
            float4 p4 = *(const float4*)&Wp[k][tx << 2];
            float am[4] = {a4.x, a4.y, a4.z, a4.w};
            float gn[4] = {g4.x, g4.y, g4.z, g4.w};
            float pn[4] = {p4.x, p4.y, p4.z, p4.w};
#pragma unroll
            for (int i = 0; i < 4; i++)
#pragma unroll
                for (int jj = 0; jj < 4; jj++) {
                    accg[i][jj] = fmaf(am[i], gn[jj], accg[i][jj]);
                    accp[i][jj] = fmaf(am[i], pn[jj], accp[i][jj]);
                }
        }
        __syncthreads();
    }
#pragma unroll
    for (int i = 0; i < 4; i++) {
        int m = bm + (ty << 2) + i;
#pragma unroll
        for (int jj = 0; jj < 4; jj++) {
            int n = bn + (tx << 2) + jj;
            g_refg[(size_t)m * N + n] = accg[i][jj] + gbr[n];
            g_refp[(size_t)m * N + n] = accp[i][jj] + pbr[n];
        }
    }
}

// warp 4-way reduce
__device__ __forceinline__ void wredd4(float& a0, float& a1, float& a2, float& a3) {
#pragma unroll
    for (int o = 16; o; o >>= 1) {
        a0 += __shfl_xor_sync(0xffffffffu, a0, o);
        a1 += __shfl_xor_sync(0xffffffffu, a1, o);
        a2 += __shfl_xor_sync(0xffffffffu, a2, o);
        a3 += __shfl_xor_sync(0xffffffffu, a3, o);
    }
}

// ---------------- persistent decoder smem layout ----------------
struct __align__(16) SmemDec {
    float hh[4][Hz];
    float cc[4][Hz];
    u64 hp[2][Hz];
    float gat[4 * 4 * Hz];
    float sbias[G4];
    float P0[G4], P1[G4];
    float qq[4][Hz];
    float qv[4][Hz];
    float Vg[Hz], Vp[Hz];
    float lg[4][128];
    float w[4][128];
    float red[4][256];
    int ridx[4][256];
    short list[4][104];
    unsigned char m[4][104];
    int ccnt[4][4];
    int idx[4];
};

// ---------------- persistent decoder: 128 blocks x 1024 thr, 4 b/block, 100 steps ----------------
__global__ void __launch_bounds__(1024, 1) k_dec_p(const float* __restrict__ inp,
                                                   const float* __restrict__ dbih,
                                                   const float* __restrict__ dbhh,
                                                   const float* __restrict__ gWq,
                                                   const float* __restrict__ gbq,
                                                   const float* __restrict__ gV,
                                                   const float* __restrict__ pWq,
                                                   const float* __restrict__ pbq,
                                                   const float* __restrict__ pV,
                                                   float* __restrict__ out) {
    extern __shared__ char smraw[];
    SmemDec* sm = (SmemDec*)smraw;

    const int tid = threadIdx.x;
    const int bb = blockIdx.x << 2;
    const int qt = tid >> 8, ht = tid & 255;
    const int wd = tid >> 5, ln = tid & 31;
    const int b = bb + qt;

    sm->hh[qt][ht] = g_h0[(b << 8) + ht];
    sm->cc[qt][ht] = g_c[(b << 8) + ht];
    sm->sbias[tid] = dbih[tid] + dbhh[tid];
    sm->P0[tid] = g_Pdec[tid];
    sm->P1[tid] = g_Pdec[G4 + tid];
    if (tid < Hz) sm->Vg[tid] = gV[tid];
    else if (tid < 2 * Hz) sm->Vp[tid - Hz] = pV[tid - Hz];
    if (ht < Sz) sm->m[qt][ht] = 0;
    if (tid < 4) sm->idx[tid] = 0;
    __syncthreads();

    float* out_probs = out;
    float* out_idx = out + (size_t)Sz * Bz * Sz;
    const float4* wt = g_WTd;

    for (int t = 0; t < Sz; t++) {
        // ---- pack h pairs ----
        if (tid < 512) {
            int pr = tid >> 8, hx = tid & 255;
            sm->hp[pr][hx] = pk2(sm->hh[2 * pr][hx], sm->hh[2 * pr + 1][hx]);
        }
        __syncthreads();
        // ---- gates matvec (bit-identical k-order) ----
        u64 a01 = pk2(0.f, 0.f), a23 = a01;
#pragma unroll 4
        for (int k4 = 0; k4 < 64; k4++) {
            float4 wv = wt[(k4 << 10) + tid];
            int k = k4 << 2;
            u64 w2;
            w2 = pk2(wv.x, wv.x); a01 = fma2(w2, sm->hp[0][k], a01);     a23 = fma2(w2, sm->hp[1][k], a23);
            w2 = pk2(wv.y, wv.y); a01 = fma2(w2, sm->hp[0][k + 1], a01); a23 = fma2(w2, sm->hp[1][k + 1], a23);
            w2 = pk2(wv.z, wv.z); a01 = fma2(w2, sm->hp[0][k + 2], a01); a23 = fma2(w2, sm->hp[1][k + 2], a23);
            w2 = pk2(wv.w, wv.w); a01 = fma2(w2, sm->hp[0][k + 3], a01); a23 = fma2(w2, sm->hp[1][k + 3], a23);
        }
        {
            float l0, l1, l2, l3;
            upk2(a01, l0, l1);
            upk2(a23, l2, l3);
            int gb = ((tid >> 8) << 10) + (tid & 255);
            sm->gat[gb] = l0; sm->gat[gb + 256] = l1; sm->gat[gb + 512] = l2; sm->gat[gb + 768] = l3;
        }
        __syncthreads();
        // ---- LSTM cell ----
        {
            float a0 = sm->gat[(qt << 8) + ht];
            float a1 = sm->gat[1024 + (qt << 8) + ht];
            float a2 = sm->gat[2048 + (qt << 8) + ht];
            float a3 = sm->gat[3072 + (qt << 8) + ht];
            float xg0, xg1, xg2, xg3;
            if (t == 0) {
                xg0 = g_startproj[ht];
                xg1 = g_startproj[256 + ht];
                xg2 = g_startproj[512 + ht];
                xg3 = g_startproj[768 + ht];
            } else {
                int s = sm->idx[qt];
                float c0 = inp[(b * 2) * Sz + s];
                float c1 = inp[(b * 2 + 1) * Sz + s];
                xg0 = fmaf(c0, sm->P0[ht],       c1 * sm->P1[ht]);
                xg1 = fmaf(c0, sm->P0[256 + ht], c1 * sm->P1[256 + ht]);
                xg2 = fmaf(c0, sm->P0[512 + ht], c1 * sm->P1[512 + ht]);
                xg3 = fmaf(c0, sm->P0[768 + ht], c1 * sm->P1[768 + ht]);
            }
            float gi = a0 + xg0 + sm->sbias[ht];
            float gf = a1 + xg1 + sm->sbias[256 + ht];
            float gc = a2 + xg2 + sm->sbias[512 + ht];
            float go = a3 + xg3 + sm->sbias[768 + ht];
            float nc = sigf(gf) * sm->cc[qt][ht] + sigf(gi) * xtanh(gc);
            sm->cc[qt][ht] = nc;
            sm->hh[qt][ht] = sigf(go) * xtanh(nc);
        }
        __syncthreads();

        // ==================== attention + sample (per-b local) ====================
        if (t > 0 && ht == 0) sm->m[qt][sm->idx[qt]] = 1;
        __syncthreads();

        // deterministic compaction of unmasked s (ascending, per quarter)
        bool un = false; int pre = 0, chunk = 0;
        if (ht < 128) {
            chunk = ht >> 5;
            un = (ht < Sz) && !sm->m[qt][ht];
            unsigned bal = __ballot_sync(0xffffffffu, un);
            pre = __popc(bal & ((1u << (ht & 31)) - 1));
            if ((ht & 31) == 0) sm->ccnt[qt][chunk] = __popc(bal);
        }
        __syncthreads();
        int nq[4];
#pragma unroll
        for (int g = 0; g < 4; g++)
            nq[g] = sm->ccnt[g][0] + sm->ccnt[g][1] + sm->ccnt[g][2] + sm->ccnt[g][3];
        const int n_self = nq[qt];
        int nmax = nq[0];
#pragma unroll
        for (int g = 1; g < 4; g++) nmax = nq[g] > nmax ? nq[g] : nmax;
        if (un) {
            int base = 0;
            for (int i = 0; i < chunk; i++) base += sm->ccnt[qt][i];
            sm->list[qt][base + pre] = (short)ht;
        }
        if (ht < 128) sm->lg[qt][ht] = -INFINITY;
        __syncthreads();

        // qq = h @ gWq^T + gbq, warp-cooperative rows for all 4 b's
        for (int row = wd; row < Hz; row += 32) {
            const float4* wr = (const float4*)(gWq + (size_t)row * Hz);
            float4 w1 = wr[ln], w2 = wr[32 + ln];
            float a[4];
#pragma unroll
            for (int g = 0; g < 4; g++) {
                float4 ha = *(const float4*)&sm->hh[g][ln << 2];
                float4 hb = *(const float4*)&sm->hh[g][128 + (ln << 2)];
                float ag = 0.f;
                ag = fmaf(w1.x, ha.x, ag); ag = fmaf(w1.y, ha.y, ag);
                ag = fmaf(w1.z, ha.z, ag); ag = fmaf(w1.w, ha.w, ag);
                ag = fmaf(w2.x, hb.x, ag); ag = fmaf(w2.y, hb.y, ag);
                ag = fmaf(w2.z, hb.z, ag); ag = fmaf(w2.w, hb.w, ag);
                a[g] = ag;
            }
            wredd4(a[0], a[1], a[2], a[3]);
            if (!ln) {
                float bq = gbq[row];
#pragma unroll
                for (int g = 0; g < 4; g++) sm->qq[g][row] = a[g] + bq;
            }
        }
        __syncthreads();
        // glimpse logits over compact lists
        for (int ii = wd; ii < nmax; ii += 32) {
            int sg[4]; float a[4];
#pragma unroll
            for (int g = 0; g < 4; g++) {
                sg[g] = (ii < nq[g]) ? sm->list[g][ii] : -1;
                a[g] = 0.f;
            }
#pragma unroll
            for (int g = 0; g < 4; g++) {
                if (sg[g] >= 0) {
                    const float4* rg = (const float4*)(g_refg + ((size_t)(bb + g) * Sz + sg[g]) * Hz);
#pragma unroll
                    for (int i = 0; i < 2; i++) {
                        int c = i * 32 + ln;
                        float4 rv = rg[c];
                        float4 qvv = *(const float4*)&sm->qq[g][c << 2];
                        float4 vv = *(const float4*)&sm->Vg[c << 2];
                        a[g] = fmaf(vv.x, xtanh(qvv.x + rv.x), a[g]);
                        a[g] = fmaf(vv.y, xtanh(qvv.y + rv.y), a[g]);
                        a[g] = fmaf(vv.z, xtanh(qvv.z + rv.z), a[g]);
                        a[g] = fmaf(vv.w, xtanh(qvv.w + rv.w), a[g]);
                    }
                }
            }
            wredd4(a[0], a[1], a[2], a[3]);
            if (!ln) {
#pragma unroll
                for (int g = 0; g < 4; g++)
                    if (sg[g] >= 0) sm->lg[g][sg[g]] = a[g];
            }
        }
        __syncthreads();
        // softmax -> w (per quarter)
        {
            float v = (ht < Sz) ? sm->lg[qt][ht] : -INFINITY;
            sm->red[qt][ht] = v; __syncthreads();
#pragma unroll
            for (int o = 128; o; o >>= 1) { if (ht < o) sm->red[qt][ht] = fmaxf(sm->red[qt][ht], sm->red[qt][ht + o]); __syncthreads(); }
            float m = sm->red[qt][0]; __syncthreads();
            float e = (ht < Sz) ? expf(v - m) : 0.f;
            sm->red[qt][ht] = e; __syncthreads();
#pragma unroll
            for (int o = 128; o; o >>= 1) { if (ht < o) sm->red[qt][ht] += sm->red[qt][ht + o]; __syncthreads(); }
            float smv = sm->red[qt][0]; __syncthreads();
            if (ht < 128) sm->w[qt][ht] = (ht < Sz) ? e / smv : 0.f;
        }
        __syncthreads();
        // q = sum over unmasked s of w[s]*enc[b,s,:]
        {
            float av[8];
#pragma unroll
            for (int i = 0; i < 8; i++) av[i] = 0.f;
            const float* eb = g_enc + (size_t)b * Sz * Hz + ht;
            int ii = 0;
            for (; ii + 8 <= n_self; ii += 8) {
#pragma unroll
                for (int i = 0; i < 8; i++) {
                    int s = sm->list[qt][ii + i];
                    av[i] = fmaf(sm->w[qt][s], eb[(size_t)s * Hz], av[i]);
                }
            }
            for (; ii < n_self; ii++) {
                int s = sm->list[qt][ii];
                av[ii & 7] = fmaf(sm->w[qt][s], eb[(size_t)s * Hz], av[ii & 7]);
            }
            sm->qv[qt][ht] = ((av[0] + av[1]) + (av[2] + av[3])) + ((av[4] + av[5]) + (av[6] + av[7]));
        }
        __syncthreads();
        // qq2 = q @ pWq^T + pbq
        for (int row = wd; row < Hz; row += 32) {
            const float4* wr = (const float4*)(pWq + (size_t)row * Hz);
            float4 w1 = wr[ln], w2 = wr[32 + ln];
            float a[4];
#pragma unroll
            for (int g = 0; g < 4; g++) {
                float4 ha = *(const float4*)&sm->qv[g][ln << 2];
                float4 hb = *(const float4*)&sm->qv[g][128 + (ln << 2)];
                float ag = 0.f;
                ag = fmaf(w1.x, ha.x, ag); ag = fmaf(w1.y, ha.y, ag);
                ag = fmaf(w1.z, ha.z, ag); ag = fmaf(w1.w, ha.w, ag);
                ag = fmaf(w2.x, hb.x, ag); ag = fmaf(w2.y, hb.y, ag);
                ag = fmaf(w2.z, hb.z, ag); ag = fmaf(w2.w, hb.w, ag);
                a[g] = ag;
            }
            wredd4(a[0], a[1], a[2], a[3]);
            if (!ln) {
                float bq = pbq[row];
#pragma unroll
                for (int g = 0; g < 4; g++) sm->qq[g][row] = a[g] + bq;
            }
        }
        __syncthreads();
        // pointer logits over compact lists
        for (int ii = wd; ii < nmax; ii += 32) {
            int sg[4]; float a[4];
#pragma unroll
            for (int g = 0; g < 4; g++) {
                sg[g] = (ii < nq[g]) ? sm->list[g][ii] : -1;
                a[g] = 0.f;
            }
#pragma unroll
            for (int g = 0; g < 4; g++) {
                if (sg[g] >= 0) {
                    const float4* rp = (const float4*)(g_refp + ((size_t)(bb + g) * Sz + sg[g]) * Hz);
#pragma unroll
                    for (int i = 0; i < 2; i++) {
                        int c = i * 32 + ln;
                        float4 rv = rp[c];
                        float4 qvv = *(const float4*)&sm->qq[g][c << 2];
                        float4 vv = *(const float4*)&sm->Vp[c << 2];
                        a[g] = fmaf(vv.x, xtanh(qvv.x + rv.x), a[g]);
                        a[g] = fmaf(vv.y, xtanh(qvv.y + rv.y), a[g]);
                        a[g] = fmaf(vv.z, xtanh(qvv.z + rv.z), a[g]);
                        a[g] = fmaf(vv.w, xtanh(qvv.w + rv.w), a[g]);
                    }
                }
            }
            wredd4(a[0], a[1], a[2], a[3]);
            if (!ln) {
#pragma unroll
                for (int g = 0; g < 4; g++)
                    if (sg[g] >= 0) sm->lg[g][sg[g]] = C_EXPLORE * xtanh(a[g]);
            }
        }
        __syncthreads();
        // softmax -> probs; gumbel argmax -> idx
        {
            float v = (ht < Sz) ? sm->lg[qt][ht] : -INFINITY;
            sm->red[qt][ht] = v; __syncthreads();
#pragma unroll
            for (int o = 128; o; o >>= 1) { if (ht < o) sm->red[qt][ht] = fmaxf(sm->red[qt][ht], sm->red[qt][ht + o]); __syncthreads(); }
            float m = sm->red[qt][0]; __syncthreads();
            float e = (ht < Sz) ? expf(v - m) : 0.f;
            sm->red[qt][ht] = e; __syncthreads();
#pragma unroll
            for (int o = 128; o; o >>= 1) { if (ht < o) sm->red[qt][ht] += sm->red[qt][ht + o]; __syncthreads(); }
            float smv = sm->red[qt][0]; __syncthreads();
            if (ht < Sz)
                out_probs[(size_t)t * Bz * Sz + (size_t)b * Sz + ht] = e / smv;
            float pv = -INFINITY;
            if (ht < Sz) {
                unsigned key0, key1;
#if PARTITIONABLE
                tf2x32(0u, 1u, 0u, (unsigned)t, key0, key1);
#else
                {
                    unsigned a0k, b0k;
                    unsigned idx0 = 2u * t, idx1 = 2u * t + 1u;
                    if (idx0 < Sz) { tf2x32(0u, 1u, idx0, idx0 + Sz, a0k, b0k); key0 = a0k; }
                    else           { tf2x32(0u, 1u, idx0 - Sz, idx0, a0k, b0k); key0 = b0k; }
                    if (idx1 < Sz) { tf2x32(0u, 1u, idx1, idx1 + Sz, a0k, b0k); key1 = a0k; }
                    else           { tf2x32(0u, 1u, idx1 - Sz, idx1, a0k, b0k); key1 = b0k; }
                }
#endif
                unsigned m0 = (unsigned)(b * Sz + ht);
                unsigned ra, rb, bits;
#if PARTITIONABLE
                tf2x32(key0, key1, 0u, m0, ra, rb);
                bits = ra ^ rb;
#else
                const unsigned halfn = (Bz * Sz) / 2;
                if (m0 < halfn) { tf2x32(key0, key1, m0, m0 + halfn, ra, rb); bits = ra; }
                else            { tf2x32(key0, key1, m0 - halfn, m0, ra, rb); bits = rb; }
#endif
                float f = __uint_as_float((bits >> 9) | 0x3f800000u) - 1.0f;
                float u = fmaxf(f, 1.17549435e-38f);
                pv = v - logf(-logf(u));
            }
            sm->red[qt][ht] = pv; sm->ridx[qt][ht] = ht; __syncthreads();
#pragma unroll
            for (int o = 128; o; o >>= 1) {
                if (ht < o) {
                    float a2 = sm->red[qt][ht], c2 = sm->red[qt][ht + o];
                    int ia = sm->ridx[qt][ht], ic = sm->ridx[qt][ht + o];
                    if (c2 > a2 || (c2 == a2 && ic < ia)) { sm->red[qt][ht] = c2; sm->ridx[qt][ht] = ic; }
                }
                __syncthreads();
            }
            if (!ht) {
                int id = sm->ridx[qt][0];
                sm->idx[qt] = id;
                out_idx[(size_t)t * Bz + b] = (float)id;
            }
        }
        __syncthreads();
    }
}

// ---------------- host ----------------
extern "C" void kernel_launch(void* const* d_in, const int* in_sizes, int n_in,
                              void* d_out, int out_size) {
    const float* in_inputs = (const float*)d_in[0];
    const float* in_emb    = (const float*)d_in[1];
    const float* in_eWih   = (const float*)d_in[2];
    const float* in_eWhh   = (const float*)d_in[3];
    const float* in_ebih   = (const float*)d_in[4];
    const float* in_ebhh   = (const float*)d_in[5];
    const float* in_dWih   = (const float*)d_in[6];
    const float* in_dWhh   = (const float*)d_in[7];
    const float* in_dbih   = (const float*)d_in[8];
    const float* in_dbhh   = (const float*)d_in[9];
    const float* in_gWq    = (const float*)d_in[10];
    const float* in_gbq    = (const float*)d_in[11];
    const float* in_gWr    = (const float*)d_in[12];
    const float* in_gbr    = (const float*)d_in[13];
    const float* in_gV     = (const float*)d_in[14];
    const float* in_pWq    = (const float*)d_in[15];
    const float* in_pbq    = (const float*)d_in[16];
    const float* in_pWr    = (const float*)d_in[17];
    const float* in_pbr    = (const float*)d_in[18];
    const float* in_pV     = (const float*)d_in[19];
    const float* in_start  = (const float*)d_in[20];
    float* out = (float*)d_out;

    static bool attr_set = false;
    if (!attr_set) {
        cudaFuncSetAttribute(k_dec_p, cudaFuncAttributeMaxDynamicSharedMemorySize,
                             (int)sizeof(SmemDec));
        attr_set = true;
    }

    k_prep<<<4, 256>>>(in_emb, in_eWih, in_dWih, in_start);
    {
        dim3 grid(256, 2);
        k_tr<<<grid, 256>>>(in_eWhh, in_dWhh);
    }
    k_enc_p<<<128, 1024>>>(in_inputs, in_ebih, in_ebhh);
    {
        dim3 grid(Hz / 64, (Bz * Sz) / 64);
        k_ref2<<<grid, 256>>>(in_gWr, in_gbr, in_pWr, in_pbr);
    }
    k_dec_p<<<128, 1024, sizeof(SmemDec)>>>(in_inputs, in_dbih, in_dbhh,
                                            in_gWq, in_gbq, in_gV,
                                            in_pWq, in_pbq, in_pV, out);
    (void)in_sizes; (void)n_in; (void)out_size;
}

// round 15
// speedup vs baseline: 1.8318x; 1.0840x over previous
#include <cuda_runtime.h>
#include <cuda_bf16.h>
#include <math.h>
#include <stdint.h>

#define Bz 512
#define Sz 100
#define Ez 256
#define Hz 256
#define G4 1024
#define C_EXPLORE 10.0f
#define PARTITIONABLE 1

typedef unsigned long long u64;

// ---------------- packed f32x2 helpers (sm_100+) ----------------
__device__ __forceinline__ u64 pk2(float lo, float hi) {
    u64 d; asm("mov.b64 %0, {%1, %2};" : "=l"(d) : "f"(lo), "f"(hi)); return d;
}
__device__ __forceinline__ void upk2(u64 v, float& lo, float& hi) {
    asm("mov.b64 {%0, %1}, %2;" : "=f"(lo), "=f"(hi) : "l"(v));
}
__device__ __forceinline__ u64 fma2(u64 a, u64 b, u64 c) {
    u64 d; asm("fma.rn.f32x2 %0, %1, %2, %3;" : "=l"(d) : "l"(a), "l"(b), "l"(c)); return d;
}

// ---------------- fast exact-enough tanh (Eigen/XLA rational + rcp NR) ----------------
__device__ __forceinline__ float xtanh(float x) {
    const float c = 7.90531110763549805f;
    float cx = fminf(fmaxf(x, -c), c);
    float r = cx * cx;
    float p = -2.76076847742355e-16f;
    p = fmaf(p, r, 2.00018790482477e-13f);
    p = fmaf(p, r, -8.60467152213735e-11f);
    p = fmaf(p, r, 5.12229709037114e-08f);
    p = fmaf(p, r, 1.48572235717979e-05f);
    p = fmaf(p, r, 6.37261928875436e-04f);
    p = fmaf(p, r, 4.89352455891786e-03f);
    float num = cx * p;
    float q = 1.19825839466702e-06f;
    q = fmaf(q, r, 1.18534705686654e-04f);
    q = fmaf(q, r, 2.26843463243900e-03f);
    q = fmaf(q, r, 4.89352518554385e-03f);
    float ri;
    asm("rcp.approx.f32 %0, %1;" : "=f"(ri) : "f"(q));
    ri = ri * fmaf(-q, ri, 2.0f);
    return num * ri;
}
__device__ __forceinline__ float sigf(float x) {
    return 0.5f + 0.5f * xtanh(0.5f * x);
}

// ---------------- device state ----------------
__device__ float g_h0[Bz * Hz];
__device__ float g_c[Bz * Hz];
__device__ float g_enc[(size_t)Bz * Sz * Hz];
__device__ float g_refg[(size_t)Bz * Sz * Hz];
__device__ float g_refp[(size_t)Bz * Sz * Hz];
__device__ float g_Penc[2 * G4];
__device__ float g_Pdec[2 * G4];
__device__ float g_startproj[G4];
__device__ float4 g_WTe[64 * G4];   // [k4][row]
__device__ float4 g_WTd[64 * G4];

// ---------------- threefry2x32 ----------------
__device__ __forceinline__ unsigned rotl32(unsigned v, int r) {
    return (v << r) | (v >> (32 - r));
}
__device__ __forceinline__ void tf2x32(unsigned k0, unsigned k1,
                                       unsigned x0, unsigned x1,
                                       unsigned& o0, unsigned& o1) {
    unsigned ks2 = 0x1BD11BDAu ^ k0 ^ k1;
    x0 += k0; x1 += k1;
#define TF_G(a,b,c,d) \
    x0 += x1; x1 = rotl32(x1,a); x1 ^= x0; \
    x0 += x1; x1 = rotl32(x1,b); x1 ^= x0; \
    x0 += x1; x1 = rotl32(x1,c); x1 ^= x0; \
    x0 += x1; x1 = rotl32(x1,d); x1 ^= x0;
    TF_G(13,15,26,6);  x0 += k1;  x1 += ks2 + 1u;
    TF_G(17,29,16,24); x0 += ks2; x1 += k0 + 2u;
    TF_G(13,15,26,6);  x0 += k0;  x1 += k1 + 3u;
    TF_G(17,29,16,24); x0 += k1;  x1 += ks2 + 4u;
    TF_G(13,15,26,6);  x0 += ks2; x1 += k0 + 5u;
#undef TF_G
    o0 = x0; o1 = x1;
}

// ---------------- setup ----------------
__global__ void k_prep(const float* __restrict__ emb,
                       const float* __restrict__ eWih,
                       const float* __restrict__ dWih,
                       const float* __restrict__ start) {
    int j = blockIdx.x * 256 + threadIdx.x;
    if (j >= G4) return;
    float pe0 = 0.f, pe1 = 0.f, pd0 = 0.f, pd1 = 0.f, sp = 0.f;
    for (int e = 0; e < Ez; e++) {
        float we = eWih[j * Ez + e], wd = dWih[j * Ez + e];
        pe0 = fmaf(emb[e], we, pe0);
        pe1 = fmaf(emb[Ez + e], we, pe1);
        pd0 = fmaf(emb[e], wd, pd0);
        pd1 = fmaf(emb[Ez + e], wd, pd1);
        sp  = fmaf(start[e], wd, sp);
    }
    g_Penc[j] = pe0; g_Penc[G4 + j] = pe1;
    g_Pdec[j] = pd0; g_Pdec[G4 + j] = pd1;
    g_startproj[j] = sp;
}

__global__ void k_tr(const float* __restrict__ eWhh, const float* __restrict__ dWhh) {
    int idx = blockIdx.x * 256 + threadIdx.x;
    const float* W = blockIdx.y ? dWhh : eWhh;
    float4* O = blockIdx.y ? g_WTd : g_WTe;
    int j = idx & (G4 - 1);
    int k4 = idx >> 10;
    O[idx] = *(const float4*)&W[(size_t)j * Hz + (k4 << 2)];
}

// ---------------- persistent encoder: 128 blocks x 1024 thr, 4 b per block ----------------
__global__ void __launch_bounds__(1024, 1) k_enc_p(const float* __restrict__ inp,
                                                   const float* __restrict__ bih,
                                                   const float* __restrict__ bhh) {
    __shared__ float hh[4][Hz];
    __shared__ float cc[4][Hz];
    __shared__ u64 hp[2][Hz];
    __shared__ float gat[4 * 4 * Hz];
    __shared__ float sbias[G4];
    __shared__ float P0[G4], P1[G4];

    const int tid = threadIdx.x;
    const int bb = blockIdx.x << 2;
    const int qt = tid >> 8, ht = tid & 255;

    hh[qt][ht] = 0.f;
    cc[qt][ht] = 0.f;
    sbias[tid] = bih[tid] + bhh[tid];
    P0[tid] = g_Penc[tid];
    P1[tid] = g_Penc[G4 + tid];
    __syncthreads();

    const float4* wt = g_WTe;
    for (int t = 0; t < Sz; t++) {
        if (tid < 512) {
            int pr = tid >> 8, hx = tid & 255;
            hp[pr][hx] = pk2(hh[2 * pr][hx], hh[2 * pr + 1][hx]);
        }
        __syncthreads();
        u64 a01 = pk2(0.f, 0.f), a23 = a01;
#pragma unroll 4
        for (int k4 = 0; k4 < 64; k4++) {
            float4 wv = wt[(k4 << 10) + tid];
            int k = k4 << 2;
            u64 w2;
            w2 = pk2(wv.x, wv.x); a01 = fma2(w2, hp[0][k], a01);     a23 = fma2(w2, hp[1][k], a23);
            w2 = pk2(wv.y, wv.y); a01 = fma2(w2, hp[0][k + 1], a01); a23 = fma2(w2, hp[1][k + 1], a23);
            w2 = pk2(wv.z, wv.z); a01 = fma2(w2, hp[0][k + 2], a01); a23 = fma2(w2, hp[1][k + 2], a23);
            w2 = pk2(wv.w, wv.w); a01 = fma2(w2, hp[0][k + 3], a01); a23 = fma2(w2, hp[1][k + 3], a23);
        }
        {
            float l0, l1, l2, l3;
            upk2(a01, l0, l1);
            upk2(a23, l2, l3);
            int gb = ((tid >> 8) << 10) + (tid & 255);
            gat[gb] = l0; gat[gb + 256] = l1; gat[gb + 512] = l2; gat[gb + 768] = l3;
        }
        __syncthreads();
        {
            float a0 = gat[(qt << 8) + ht];
            float a1 = gat[1024 + (qt << 8) + ht];
            float a2 = gat[2048 + (qt << 8) + ht];
            float a3 = gat[3072 + (qt << 8) + ht];
            int b = bb + qt;
            float c0 = inp[(b * 2) * Sz + t];
            float c1 = inp[(b * 2 + 1) * Sz + t];
            float gi = a0 + fmaf(c0, P0[ht],        c1 * P1[ht])        + sbias[ht];
            float gf = a1 + fmaf(c0, P0[256 + ht],  c1 * P1[256 + ht])  + sbias[256 + ht];
            float gc = a2 + fmaf(c0, P0[512 + ht],  c1 * P1[512 + ht])  + sbias[512 + ht];
            float go = a3 + fmaf(c0, P0[768 + ht],  c1 * P1[768 + ht])  + sbias[768 + ht];
            float nc = sigf(gf) * cc[qt][ht] + sigf(gi) * xtanh(gc);
            cc[qt][ht] = nc;
            float nh = sigf(go) * xtanh(nc);
            hh[qt][ht] = nh;
            g_enc[((size_t)(bb + qt) * Sz + t) * Hz + ht] = nh;
        }
        __syncthreads();
    }
    {
        int b = bb + qt;
        g_h0[(b << 8) + ht] = hh[qt][ht];
        g_c[(b << 8) + ht] = cc[qt][ht];
    }
}

// ---------------- FUSED ref projections ----------------
__global__ void __launch_bounds__(256) k_ref2(const float* __restrict__ gWr,
                                              const float* __restrict__ gbr,
                                              const float* __restrict__ pWr,
                                              const float* __restrict__ pbr) {
    __shared__ float As[16][64];
    __shared__ float Wg[16][64];
    __shared__ float Wp[16][64];
    const float* A = g_enc;
    const int K = Hz, N = Hz;
    const int bm = blockIdx.y * 64;
    const int bn = blockIdx.x * 64;
    const int t = threadIdx.x;
    const int tx = t & 15, ty = t >> 4;
    const int lr = t >> 2, lc = (t & 3) << 2;
    float accg[4][4], accp[4][4];
#pragma unroll
    for (int i = 0; i < 4; i++)
#pragma unroll
        for (int jj = 0; jj < 4; jj++) { accg[i][jj] = 0.f; accp[i][jj] = 0.f; }
    const float* Ab = A + (size_t)(bm + lr) * K + lc;
    const float* Wgb = gWr + (size_t)(bn + lr) * K + lc;
    const float* Wpb = pWr + (size_t)(bn + lr) * K + lc;
    for (int k0 = 0; k0 < K; k0 += 16) {
        float4 av = *(const float4*)(Ab + k0);
        float4 gv = *(const float4*)(Wgb + k0);
        float4 pv = *(const float4*)(Wpb + k0);
        As[lc + 0][lr] = av.x; As[lc + 1][lr] = av.y;
        As[lc + 2][lr] = av.z; As[lc + 3][lr] = av.w;
        Wg[lc + 0][lr] = gv.x; Wg[lc + 1][lr] = gv.y;
        Wg[lc + 2][lr] = gv.z; Wg[lc + 3][lr] = gv.w;
        Wp[lc + 0][lr] = pv.x; Wp[lc + 1][lr] = pv.y;
        Wp[lc + 2][lr] = pv.z; Wp[lc + 3][lr] = pv.w;
        __syncthreads();
#pragma unroll
        for (int k = 0; k < 16; k++) {
            float4 a4 = *(const float4*)&As[k][ty << 2];
            float4 g4 = *(const float4*)&Wg[k][tx << 2];
            float4 p4 = *(const float4*)&Wp[k][tx << 2];
            float am[4] = {a4.x, a4.y, a4.z, a4.w};
            float gn[4] = {g4.x, g4.y, g4.z, g4.w};
            float pn[4] = {p4.x, p4.y, p4.z, p4.w};
#pragma unroll
            for (int i = 0; i < 4; i++)
#pragma unroll
                for (int jj = 0; jj < 4; jj++) {
                    accg[i][jj] = fmaf(am[i], gn[jj], accg[i][jj]);
                    accp[i][jj] = fmaf(am[i], pn[jj], accp[i][jj]);
                }
        }
        __syncthreads();
    }
#pragma unroll
    for (int i = 0; i < 4; i++) {
        int m = bm + (ty << 2) + i;
#pragma unroll
        for (int jj = 0; jj < 4; jj++) {
            int n = bn + (tx << 2) + jj;
            g_refg[(size_t)m * N + n] = accg[i][jj] + gbr[n];
            g_refp[(size_t)m * N + n] = accp[i][jj] + pbr[n];
        }
    }
}

// warp 4-way reduce
__device__ __forceinline__ void wredd4(float& a0, float& a1, float& a2, float& a3) {
#pragma unroll
    for (int o = 16; o; o >>= 1) {
        a0 += __shfl_xor_sync(0xffffffffu, a0, o);
        a1 += __shfl_xor_sync(0xffffffffu, a1, o);
        a2 += __shfl_xor_sync(0xffffffffu, a2, o);
        a3 += __shfl_xor_sync(0xffffffffu, a3, o);
    }
}

// ---------------- persistent decoder smem layout ----------------
struct __align__(16) SmemDec {
    float hh[4][Hz];
    float cc[4][Hz];
    u64 hp[2][Hz];
    float gat[4 * 4 * Hz];
    float sbias[G4];
    float P0[G4], P1[G4];
    float qq[4][Hz];
    float qv[4][Hz];
    float Vg[Hz], Vp[Hz];
    float lg[4][128];
    float w[4][128];
    float red8a[4][8];
    float red8b[4][8];
    int ridx8[4][8];
    short list[4][104];
    unsigned char m[4][104];
    int ccnt[4][4];
    int idx[4];
};

// ---------------- persistent decoder: 128 blocks x 1024 thr, 4 b/block ----------------
__global__ void __launch_bounds__(1024, 1) k_dec_p(const float* __restrict__ inp,
                                                   const float* __restrict__ dbih,
                                                   const float* __restrict__ dbhh,
                                                   const float* __restrict__ gWq,
                                                   const float* __restrict__ gbq,
                                                   const float* __restrict__ gV,
                                                   const float* __restrict__ pWq,
                                                   const float* __restrict__ pbq,
                                                   const float* __restrict__ pV,
                                                   float* __restrict__ out) {
    extern __shared__ char smraw[];
    SmemDec* sm = (SmemDec*)smraw;

    const int tid = threadIdx.x;
    const int bb = blockIdx.x << 2;
    const int qt = tid >> 8, ht = tid & 255;
    const int wd = tid >> 5, ln = tid & 31;
    const int wq = wd & 7;               // warp within quarter
    const int b = bb + qt;

    sm->hh[qt][ht] = g_h0[(b << 8) + ht];
    sm->cc[qt][ht] = g_c[(b << 8) + ht];
    sm->sbias[tid] = dbih[tid] + dbhh[tid];
    sm->P0[tid] = g_Pdec[tid];
    sm->P1[tid] = g_Pdec[G4 + tid];
    if (tid < Hz) sm->Vg[tid] = gV[tid];
    else if (tid < 2 * Hz) sm->Vp[tid - Hz] = pV[tid - Hz];
    if (ht < Sz) sm->m[qt][ht] = 0;
    if (tid < 4) sm->idx[tid] = 0;
    __syncthreads();

    float* out_probs = out;
    float* out_idx = out + (size_t)Sz * Bz * Sz;
    const float4* wt = g_WTd;

    for (int t = 0; t < Sz; t++) {
        // ---- pack h pairs ----
        if (tid < 512) {
            int pr = tid >> 8, hx = tid & 255;
            sm->hp[pr][hx] = pk2(sm->hh[2 * pr][hx], sm->hh[2 * pr + 1][hx]);
        }
        __syncthreads();
        // ---- gates matvec (bit-identical k-order) ----
        u64 a01 = pk2(0.f, 0.f), a23 = a01;
#pragma unroll 4
        for (int k4 = 0; k4 < 64; k4++) {
            float4 wv = wt[(k4 << 10) + tid];
            int k = k4 << 2;
            u64 w2;
            w2 = pk2(wv.x, wv.x); a01 = fma2(w2, sm->hp[0][k], a01);     a23 = fma2(w2, sm->hp[1][k], a23);
            w2 = pk2(wv.y, wv.y); a01 = fma2(w2, sm->hp[0][k + 1], a01); a23 = fma2(w2, sm->hp[1][k + 1], a23);
            w2 = pk2(wv.z, wv.z); a01 = fma2(w2, sm->hp[0][k + 2], a01); a23 = fma2(w2, sm->hp[1][k + 2], a23);
            w2 = pk2(wv.w, wv.w); a01 = fma2(w2, sm->hp[0][k + 3], a01); a23 = fma2(w2, sm->hp[1][k + 3], a23);
        }
        {
            float l0, l1, l2, l3;
            upk2(a01, l0, l1);
            upk2(a23, l2, l3);
            int gb = ((tid >> 8) << 10) + (tid & 255);
            sm->gat[gb] = l0; sm->gat[gb + 256] = l1; sm->gat[gb + 512] = l2; sm->gat[gb + 768] = l3;
        }
        __syncthreads();
        // ---- LSTM cell ----
        {
            float a0 = sm->gat[(qt << 8) + ht];
            float a1 = sm->gat[1024 + (qt << 8) + ht];
            float a2 = sm->gat[2048 + (qt << 8) + ht];
            float a3 = sm->gat[3072 + (qt << 8) + ht];
            float xg0, xg1, xg2, xg3;
            if (t == 0) {
                xg0 = g_startproj[ht];
                xg1 = g_startproj[256 + ht];
                xg2 = g_startproj[512 + ht];
                xg3 = g_startproj[768 + ht];
            } else {
                int s = sm->idx[qt];
                float c0 = inp[(b * 2) * Sz + s];
                float c1 = inp[(b * 2 + 1) * Sz + s];
                xg0 = fmaf(c0, sm->P0[ht],       c1 * sm->P1[ht]);
                xg1 = fmaf(c0, sm->P0[256 + ht], c1 * sm->P1[256 + ht]);
                xg2 = fmaf(c0, sm->P0[512 + ht], c1 * sm->P1[512 + ht]);
                xg3 = fmaf(c0, sm->P0[768 + ht], c1 * sm->P1[768 + ht]);
            }
            float gi = a0 + xg0 + sm->sbias[ht];
            float gf = a1 + xg1 + sm->sbias[256 + ht];
            float gc = a2 + xg2 + sm->sbias[512 + ht];
            float go = a3 + xg3 + sm->sbias[768 + ht];
            float nc = sigf(gf) * sm->cc[qt][ht] + sigf(gi) * xtanh(gc);
            sm->cc[qt][ht] = nc;
            sm->hh[qt][ht] = sigf(go) * xtanh(nc);
        }
        __syncthreads();

        // ---- mask update + compaction ----
        if (t > 0 && ht == 0) sm->m[qt][sm->idx[qt]] = 1;
        __syncthreads();
        bool un = false; int pre = 0, chunk = 0;
        if (ht < 128) {
            chunk = ht >> 5;
            un = (ht < Sz) && !sm->m[qt][ht];
            unsigned bal = __ballot_sync(0xffffffffu, un);
            pre = __popc(bal & ((1u << (ht & 31)) - 1));
            if ((ht & 31) == 0) sm->ccnt[qt][chunk] = __popc(bal);
        }
        __syncthreads();
        int nq[4];
#pragma unroll
        for (int g = 0; g < 4; g++)
            nq[g] = sm->ccnt[g][0] + sm->ccnt[g][1] + sm->ccnt[g][2] + sm->ccnt[g][3];
        const int n_self = nq[qt];
        int nmax = nq[0];
#pragma unroll
        for (int g = 1; g < 4; g++) nmax = nq[g] > nmax ? nq[g] : nmax;
        if (un) {
            int base = 0;
            for (int i = 0; i < chunk; i++) base += sm->ccnt[qt][i];
            sm->list[qt][base + pre] = (short)ht;
        }
        if (ht < 128) sm->lg[qt][ht] = -INFINITY;
        __syncthreads();

        // ---- qq = h @ gWq^T + gbq (warp-cooperative, all 4 b's) ----
        for (int row = wd; row < Hz; row += 32) {
            const float4* wr = (const float4*)(gWq + (size_t)row * Hz);
            float4 w1 = wr[ln], w2 = wr[32 + ln];
            float a[4];
#pragma unroll
            for (int g = 0; g < 4; g++) {
                float4 ha = *(const float4*)&sm->hh[g][ln << 2];
                float4 hb = *(const float4*)&sm->hh[g][128 + (ln << 2)];
                float ag = 0.f;
                ag = fmaf(w1.x, ha.x, ag); ag = fmaf(w1.y, ha.y, ag);
                ag = fmaf(w1.z, ha.z, ag); ag = fmaf(w1.w, ha.w, ag);
                ag = fmaf(w2.x, hb.x, ag); ag = fmaf(w2.y, hb.y, ag);
                ag = fmaf(w2.z, hb.z, ag); ag = fmaf(w2.w, hb.w, ag);
                a[g] = ag;
            }
            wredd4(a[0], a[1], a[2], a[3]);
            if (!ln) {
                float bq = gbq[row];
#pragma unroll
                for (int g = 0; g < 4; g++) sm->qq[g][row] = a[g] + bq;
            }
        }
        __syncthreads();
        // ---- glimpse logits over compact lists ----
        for (int ii = wd; ii < nmax; ii += 32) {
            int sg[4]; float a[4];
#pragma unroll
            for (int g = 0; g < 4; g++) {
                sg[g] = (ii < nq[g]) ? sm->list[g][ii] : -1;
                a[g] = 0.f;
            }
#pragma unroll
            for (int g = 0; g < 4; g++) {
                if (sg[g] >= 0) {
                    const float4* rg = (const float4*)(g_refg + ((size_t)(bb + g) * Sz + sg[g]) * Hz);
#pragma unroll
                    for (int i = 0; i < 2; i++) {
                        int c = i * 32 + ln;
                        float4 rv = rg[c];
                        float4 qvv = *(const float4*)&sm->qq[g][c << 2];
                        float4 vv = *(const float4*)&sm->Vg[c << 2];
                        a[g] = fmaf(vv.x, xtanh(qvv.x + rv.x), a[g]);
                        a[g] = fmaf(vv.y, xtanh(qvv.y + rv.y), a[g]);
                        a[g] = fmaf(vv.z, xtanh(qvv.z + rv.z), a[g]);
                        a[g] = fmaf(vv.w, xtanh(qvv.w + rv.w), a[g]);
                    }
                }
            }
            wredd4(a[0], a[1], a[2], a[3]);
            if (!ln) {
#pragma unroll
                for (int g = 0; g < 4; g++)
                    if (sg[g] >= 0) sm->lg[g][sg[g]] = a[g];
            }
        }
        __syncthreads();
        // ---- glimpse softmax (warp-shuffle reduction; 2 syncs) ----
        {
            float v = (ht < Sz) ? sm->lg[qt][ht] : -INFINITY;
            float wm = v;
#pragma unroll
            for (int o = 16; o; o >>= 1) wm = fmaxf(wm, __shfl_xor_sync(0xffffffffu, wm, o));
            if (!ln) sm->red8a[qt][wq] = wm;
            __syncthreads();
            float m = sm->red8a[qt][0];
#pragma unroll
            for (int g = 1; g < 8; g++) m = fmaxf(m, sm->red8a[qt][g]);
            float e = (ht < Sz) ? expf(v - m) : 0.f;
            float ws = e;
#pragma unroll
            for (int o = 16; o; o >>= 1) ws += __shfl_xor_sync(0xffffffffu, ws, o);
            if (!ln) sm->red8b[qt][wq] = ws;
            __syncthreads();
            float smv = 0.f;
#pragma unroll
            for (int g = 0; g < 8; g++) smv += sm->red8b[qt][g];
            if (ht < 128) sm->w[qt][ht] = (ht < Sz) ? e / smv : 0.f;
        }
        __syncthreads();
        // ---- q = sum over unmasked s of w[s]*enc[b,s,:] ----
        {
            float av[8];
#pragma unroll
            for (int i = 0; i < 8; i++) av[i] = 0.f;
            const float* eb = g_enc + (size_t)b * Sz * Hz + ht;
            int ii = 0;
            for (; ii + 8 <= n_self; ii += 8) {
#pragma unroll
                for (int i = 0; i < 8; i++) {
                    int s = sm->list[qt][ii + i];
                    av[i] = fmaf(sm->w[qt][s], eb[(size_t)s * Hz], av[i]);
                }
            }
            for (; ii < n_self; ii++) {
                int s = sm->list[qt][ii];
                av[ii & 7] = fmaf(sm->w[qt][s], eb[(size_t)s * Hz], av[ii & 7]);
            }
            sm->qv[qt][ht] = ((av[0] + av[1]) + (av[2] + av[3])) + ((av[4] + av[5]) + (av[6] + av[7]));
        }
        __syncthreads();
        // ---- qq2 = q @ pWq^T + pbq ----
        for (int row = wd; row < Hz; row += 32) {
            const float4* wr = (const float4*)(pWq + (size_t)row * Hz);
            float4 w1 = wr[ln], w2 = wr[32 + ln];
            float a[4];
#pragma unroll
            for (int g = 0; g < 4; g++) {
                float4 ha = *(const float4*)&sm->qv[g][ln << 2];
                float4 hb = *(const float4*)&sm->qv[g][128 + (ln << 2)];
                float ag = 0.f;
                ag = fmaf(w1.x, ha.x, ag); ag = fmaf(w1.y, ha.y, ag);
                ag = fmaf(w1.z, ha.z, ag); ag = fmaf(w1.w, ha.w, ag);
                ag = fmaf(w2.x, hb.x, ag); ag = fmaf(w2.y, hb.y, ag);
                ag = fmaf(w2.z, hb.z, ag); ag = fmaf(w2.w, hb.w, ag);
                a[g] = ag;
            }
            wredd4(a[0], a[1], a[2], a[3]);
            if (!ln) {
                float bq = pbq[row];
#pragma unroll
                for (int g = 0; g < 4; g++) sm->qq[g][row] = a[g] + bq;
            }
        }
        __syncthreads();
        // ---- pointer logits over compact lists ----
        for (int ii = wd; ii < nmax; ii += 32) {
            int sg[4]; float a[4];
#pragma unroll
            for (int g = 0; g < 4; g++) {
                sg[g] = (ii < nq[g]) ? sm->list[g][ii] : -1;
                a[g] = 0.f;
            }
#pragma unroll
            for (int g = 0; g < 4; g++) {
                if (sg[g] >= 0) {
                    const float4* rp = (const float4*)(g_refp + ((size_t)(bb + g) * Sz + sg[g]) * Hz);
#pragma unroll
                    for (int i = 0; i < 2; i++) {
                        int c = i * 32 + ln;
                        float4 rv = rp[c];
                        float4 qvv = *(const float4*)&sm->qq[g][c << 2];
                        float4 vv = *(const float4*)&sm->Vp[c << 2];
                        a[g] = fmaf(vv.x, xtanh(qvv.x + rv.x), a[g]);
                        a[g] = fmaf(vv.y, xtanh(qvv.y + rv.y), a[g]);
                        a[g] = fmaf(vv.z, xtanh(qvv.z + rv.z), a[g]);
                        a[g] = fmaf(vv.w, xtanh(qvv.w + rv.w), a[g]);
                    }
                }
            }
            wredd4(a[0], a[1], a[2], a[3]);
            if (!ln) {
#pragma unroll
                for (int g = 0; g < 4; g++)
                    if (sg[g] >= 0) sm->lg[g][sg[g]] = C_EXPLORE * xtanh(a[g]);
            }
        }
        __syncthreads();
        // ---- pointer softmax + probs + gumbel argmax (warp-shuffle; 3 syncs) ----
        {
            float v = (ht < Sz) ? sm->lg[qt][ht] : -INFINITY;
            float wm = v;
#pragma unroll
            for (int o = 16; o; o >>= 1) wm = fmaxf(wm, __shfl_xor_sync(0xffffffffu, wm, o));
            if (!ln) sm->red8a[qt][wq] = wm;
            __syncthreads();
            float m = sm->red8a[qt][0];
#pragma unroll
            for (int g = 1; g < 8; g++) m = fmaxf(m, sm->red8a[qt][g]);
            float e = (ht < Sz) ? expf(v - m) : 0.f;
            float ws = e;
#pragma unroll
            for (int o = 16; o; o >>= 1) ws += __shfl_xor_sync(0xffffffffu, ws, o);
            if (!ln) sm->red8b[qt][wq] = ws;
            __syncthreads();
            float smv = 0.f;
#pragma unroll
            for (int g = 0; g < 8; g++) smv += sm->red8b[qt][g];
            if (ht < Sz)
                out_probs[(size_t)t * Bz * Sz + (size_t)b * Sz + ht] = e / smv;
            // gumbel perturbation + warp argmax
            float pv = -INFINITY;
            if (ht < Sz) {
                unsigned key0, key1;
#if PARTITIONABLE
                tf2x32(0u, 1u, 0u, (unsigned)t, key0, key1);
#else
                {
                    unsigned a0k, b0k;
                    unsigned idx0 = 2u * t, idx1 = 2u * t + 1u;
                    if (idx0 < Sz) { tf2x32(0u, 1u, idx0, idx0 + Sz, a0k, b0k); key0 = a0k; }
                    else           { tf2x32(0u, 1u, idx0 - Sz, idx0, a0k, b0k); key0 = b0k; }
                    if (idx1 < Sz) { tf2x32(0u, 1u, idx1, idx1 + Sz, a0k, b0k); key1 = a0k; }
                    else           { tf2x32(0u, 1u, idx1 - Sz, idx1, a0k, b0k); key1 = b0k; }
                }
#endif
                unsigned m0 = (unsigned)(b * Sz + ht);
                unsigned ra, rb, bits;
#if PARTITIONABLE
                tf2x32(key0, key1, 0u, m0, ra, rb);
                bits = ra ^ rb;
#else
                const unsigned halfn = (Bz * Sz) / 2;
                if (m0 < halfn) { tf2x32(key0, key1, m0, m0 + halfn, ra, rb); bits = ra; }
                else            { tf2x32(key0, key1, m0 - halfn, m0, ra, rb); bits = rb; }
#endif
                float f = __uint_as_float((bits >> 9) | 0x3f800000u) - 1.0f;
                float u = fmaxf(f, 1.17549435e-38f);
                pv = v - logf(-logf(u));
            }
            int ai = ht;
#pragma unroll
            for (int o = 16; o; o >>= 1) {
                float ov = __shfl_xor_sync(0xffffffffu, pv, o);
                int oi = __shfl_xor_sync(0xffffffffu, ai, o);
                if (ov > pv || (ov == pv && oi < ai)) { pv = ov; ai = oi; }
            }
            if (!ln) { sm->red8a[qt][wq] = pv; sm->ridx8[qt][wq] = ai; }
            __syncthreads();
            if (ht == 0) {
                float bv = sm->red8a[qt][0];
                int bi = sm->ridx8[qt][0];
#pragma unroll
                for (int g = 1; g < 8; g++) {
                    float cv = sm->red8a[qt][g];
                    int ci = sm->ridx8[qt][g];
                    if (cv > bv || (cv == bv && ci < bi)) { bv = cv; bi = ci; }
                }
                sm->idx[qt] = bi;
                out_idx[(size_t)t * Bz + b] = (float)bi;
            }
        }
        __syncthreads();
    }
}

// ---------------- host ----------------
extern "C" void kernel_launch(void* const* d_in, const int* in_sizes, int n_in,
                              void* d_out, int out_size) {
    const float* in_inputs = (const float*)d_in[0];
    const float* in_emb    = (const float*)d_in[1];
    const float* in_eWih   = (const float*)d_in[2];
    const float* in_eWhh   = (const float*)d_in[3];
    const float* in_ebih   = (const float*)d_in[4];
    const float* in_ebhh   = (const float*)d_in[5];
    const float* in_dWih   = (const float*)d_in[6];
    const float* in_dWhh   = (const float*)d_in[7];
    const float* in_dbih   = (const float*)d_in[8];
    const float* in_dbhh   = (const float*)d_in[9];
    const float* in_gWq    = (const float*)d_in[10];
    const float* in_gbq    = (const float*)d_in[11];
    const float* in_gWr    = (const float*)d_in[12];
    const float* in_gbr    = (const float*)d_in[13];
    const float* in_gV     = (const float*)d_in[14];
    const float* in_pWq    = (const float*)d_in[15];
    const float* in_pbq    = (const float*)d_in[16];
    const float* in_pWr    = (const float*)d_in[17];
    const float* in_pbr    = (const float*)d_in[18];
    const float* in_pV     = (const float*)d_in[19];
    const float* in_start  = (const float*)d_in[20];
    float* out = (float*)d_out;

    cudaFuncSetAttribute(k_dec_p, cudaFuncAttributeMaxDynamicSharedMemorySize,
                         (int)sizeof(SmemDec));

    k_prep<<<4, 256>>>(in_emb, in_eWih, in_dWih, in_start);
    {
        dim3 grid(256, 2);
        k_tr<<<grid, 256>>>(in_eWhh, in_dWhh);
    }
    k_enc_p<<<128, 1024>>>(in_inputs, in_ebih, in_ebhh);
    {
        dim3 grid(Hz / 64, (Bz * Sz) / 64);
        k_ref2<<<grid, 256>>>(in_gWr, in_gbr, in_pWr, in_pbr);
    }
    k_dec_p<<<128, 1024, sizeof(SmemDec)>>>(in_inputs, in_dbih, in_dbhh,
                                            in_gWq, in_gbq, in_gV,
                                            in_pWq, in_pbq, in_pV, out);
    (void)in_sizes; (void)n_in; (void)out_size;
}